// round 14
// baseline (speedup 1.0000x reference)
#include <cuda_runtime.h>
#include <cuda_bf16.h>
#include <cstddef>
#include <cstdint>

// ---------------------------------------------------------------------------
// Problem constants
// ---------------------------------------------------------------------------
#define BB   8
#define NN   64
#define TT   (BB * NN * NN)      // 32768 tokens
#define DD   128
#define HH   4
#define DHH  32
#define LL   3
#define FFD  512

// QKV offsets inside fused 512-wide projection
#define Q_OFF   0
#define K_OFF   128
#define V1_OFF  256
#define V2_OFF  384

static __device__ float g_tok [TT * DD];    // token buffer       (16 MB)
static __device__ float g_big [TT * FFD];   // QKV fused / FFN hidden (64 MB)
static __device__ float g_o   [TT * DD];    // attention output   (16 MB)
static __device__ float g_wpk [LL * DD * 4 * DD];  // packed QKV weights

// ---------------------------------------------------------------------------
// cp.async helpers
// ---------------------------------------------------------------------------
__device__ __forceinline__ void cp16(uint32_t dst, const void* src) {
    asm volatile("cp.async.cg.shared.global [%0], [%1], 16;\n"
                 :: "r"(dst), "l"(src) : "memory");
}
__device__ __forceinline__ void cp_commit() {
    asm volatile("cp.async.commit_group;\n" ::: "memory");
}
template <int N> __device__ __forceinline__ void cp_wait() {
    asm volatile("cp.async.wait_group %0;\n" :: "n"(N) : "memory");
}

// ---------------------------------------------------------------------------
// packed f32x2 helpers (Blackwell FFMA2 path; exact fp32 semantics)
// ---------------------------------------------------------------------------
__device__ __forceinline__ unsigned long long splat2(float v) {
    unsigned long long r; uint32_t u = __float_as_uint(v);
    asm("mov.b64 %0, {%1, %1};" : "=l"(r) : "r"(u));
    return r;
}
__device__ __forceinline__ unsigned long long fma2(
    unsigned long long a, unsigned long long b, unsigned long long c) {
    unsigned long long d;
    asm("fma.rn.f32x2 %0, %1, %2, %3;" : "=l"(d) : "l"(a), "l"(b), "l"(c));
    return d;
}
__device__ __forceinline__ float2 unpack2(unsigned long long v) {
    uint32_t lo, hi;
    asm("mov.b64 {%0, %1}, %2;" : "=r"(lo), "=r"(hi) : "l"(v));
    return make_float2(__uint_as_float(lo), __uint_as_float(hi));
}
__device__ __forceinline__ unsigned long long d2ll(double v) {
    return __double_as_longlong(v);
}

// ---------------------------------------------------------------------------
// Pack Wq|Wk|Wv1|Wv2 -> wpack[l][k][512]
// ---------------------------------------------------------------------------
__global__ __launch_bounds__(512) void pack_w_kernel(
    const float* __restrict__ Wq, const float* __restrict__ Wk,
    const float* __restrict__ Wv1, const float* __restrict__ Wv2,
    float* __restrict__ wpk)
{
    int lk = blockIdx.x;           // l*128 + k
    int l  = lk >> 7;
    int k  = lk & 127;
    int n  = threadIdx.x;          // 0..511
    int c  = n & 127;
    const float* src;
    switch (n >> 7) {
        case 0:  src = Wq;  break;
        case 1:  src = Wk;  break;
        case 2:  src = Wv1; break;
        default: src = Wv2; break;
    }
    wpk[(size_t)lk * 512 + n] = src[(size_t)l * DD * DD + k * DD + c];
}

// ---------------------------------------------------------------------------
// Embedding: tok[b,i,j,:] = node/edge/no_edge
// ---------------------------------------------------------------------------
__global__ __launch_bounds__(128) void embed_kernel(
    const float* __restrict__ x, const float* __restrict__ ea,
    const int*   __restrict__ mask,
    const float* __restrict__ nW, const float* __restrict__ nb,
    const float* __restrict__ eW, const float* __restrict__ eb,
    const float* __restrict__ noe, float* __restrict__ tok)
{
    int t = blockIdx.x;
    int d = threadIdx.x;
    int b = t >> 12;
    int i = (t >> 6) & 63;
    int j = t & 63;

    float val;
    if (i == j) {
        val = nb[d];
        const float* xr = x + (size_t)(b * NN + i) * 16;
#pragma unroll
        for (int c = 0; c < 16; c++) val = fmaf(xr[c], nW[c * DD + d], val);
    } else if (mask[t] != 0) {
        val = eb[d];
        const float* er = ea + (size_t)t * 8;
#pragma unroll
        for (int c = 0; c < 8; c++) val = fmaf(er[c], eW[c * DD + d], val);
    } else {
        val = noe[d];
    }
    tok[(size_t)t * DD + d] = val;
}

// ---------------------------------------------------------------------------
// Tiled fp32 GEMM, packed-f32x2 (FFMA2) inner loop, M-paired accumulators.
// B is stored duplicated in SMEM as {w,w} u64 pairs -> splat comes from a
// broadcast LDS.64 (no MOV.b64 in the mainloop).
// MODE: 0 plain, 1 +bias, 2 +bias+relu, 3 +bias+residual+LayerNorm (Nc==128,
// single n-block: each CTA owns complete token rows).
// 64(M) x 128(N) tile, BK=16, 128 threads, 8x8 thread tile, double-buffered.
// ---------------------------------------------------------------------------
template <int MODE>
__global__ __launch_bounds__(128) void gemm_kernel(
    const float* __restrict__ A, const float* __restrict__ W,
    const float* __restrict__ bias, float* __restrict__ C,
    int M, int K, int Nc,
    const float* __restrict__ resid,   // MODE 3: residual input
    const float* __restrict__ lng,     // MODE 3: LN gamma
    const float* __restrict__ lnb)     // MODE 3: LN beta
{
    __shared__ float              As [2][16][68];    // [k][m], m-contiguous
    __shared__ unsigned long long Bs2[2][16][128];   // duplicated {w,w} pairs

    int tid  = threadIdx.x;
    int row0 = blockIdx.y * 64;
    int n0   = blockIdx.x * 128;

    int tx = tid & 15, ty = tid >> 4;
    int tm0 = ty * 8, tn0 = tx * 8;

    // acc2[p][j]: m-pair (tm0+2p, tm0+2p+1) x n (tn0+j)
    unsigned long long acc2[4][8];
#pragma unroll
    for (int p = 0; p < 4; p++)
#pragma unroll
        for (int j = 0; j < 8; j++) acc2[p][j] = 0ull;

    int ar  = tid >> 2;
    int ac4 = tid & 3;
    int br  = tid >> 5;
    int bc4 = tid & 31;

    float4 areg[2], breg[4];
    const int NIT = K >> 4;

#pragma unroll
    for (int rr = 0; rr < 2; rr++)
        areg[rr] = *reinterpret_cast<const float4*>(
            &A[(size_t)(row0 + ar + rr * 32) * K + ac4 * 4]);
#pragma unroll
    for (int rr = 0; rr < 4; rr++)
        breg[rr] = *reinterpret_cast<const float4*>(
            &W[(size_t)(br + rr * 4) * Nc + n0 + bc4 * 4]);
#pragma unroll
    for (int rr = 0; rr < 2; rr++) {
        int m = ar + rr * 32;
        As[0][ac4 * 4 + 0][m] = areg[rr].x;
        As[0][ac4 * 4 + 1][m] = areg[rr].y;
        As[0][ac4 * 4 + 2][m] = areg[rr].z;
        As[0][ac4 * 4 + 3][m] = areg[rr].w;
    }
#pragma unroll
    for (int rr = 0; rr < 4; rr++) {
        unsigned long long* bp = &Bs2[0][br + rr * 4][bc4 * 4];
        bp[0] = splat2(breg[rr].x); bp[1] = splat2(breg[rr].y);
        bp[2] = splat2(breg[rr].z); bp[3] = splat2(breg[rr].w);
    }
    __syncthreads();

    for (int it = 0; it < NIT; it++) {
        int cur = it & 1;
        if (it + 1 < NIT) {
            int k0 = (it + 1) << 4;
#pragma unroll
            for (int rr = 0; rr < 2; rr++)
                areg[rr] = *reinterpret_cast<const float4*>(
                    &A[(size_t)(row0 + ar + rr * 32) * K + k0 + ac4 * 4]);
#pragma unroll
            for (int rr = 0; rr < 4; rr++)
                breg[rr] = *reinterpret_cast<const float4*>(
                    &W[(size_t)(k0 + br + rr * 4) * Nc + n0 + bc4 * 4]);
        }
#pragma unroll
        for (int k = 0; k < 16; k++) {
            // A m-pairs: 2 x LDS.128 (As row stride 272B = 16B multiple)
            const double* ad = reinterpret_cast<const double*>(&As[cur][k][tm0]);
            unsigned long long a2[4];
#pragma unroll
            for (int p = 0; p < 4; p++) a2[p] = d2ll(ad[p]);
            // B splats: 8 x broadcast LDS.64 from duplicated pairs
            const unsigned long long* b2 = &Bs2[cur][k][tn0];
            unsigned long long b2r[8];
#pragma unroll
            for (int j = 0; j < 8; j++) b2r[j] = b2[j];
#pragma unroll
            for (int p = 0; p < 4; p++)
#pragma unroll
                for (int j = 0; j < 8; j++)
                    acc2[p][j] = fma2(a2[p], b2r[j], acc2[p][j]);
        }
        if (it + 1 < NIT) {
            int nxt = cur ^ 1;
#pragma unroll
            for (int rr = 0; rr < 2; rr++) {
                int m = ar + rr * 32;
                As[nxt][ac4 * 4 + 0][m] = areg[rr].x;
                As[nxt][ac4 * 4 + 1][m] = areg[rr].y;
                As[nxt][ac4 * 4 + 2][m] = areg[rr].z;
                As[nxt][ac4 * 4 + 3][m] = areg[rr].w;
            }
#pragma unroll
            for (int rr = 0; rr < 4; rr++) {
                unsigned long long* bp = &Bs2[nxt][br + rr * 4][bc4 * 4];
                bp[0] = splat2(breg[rr].x); bp[1] = splat2(breg[rr].y);
                bp[2] = splat2(breg[rr].z); bp[3] = splat2(breg[rr].w);
            }
        }
        __syncthreads();
    }

    // ---------------- epilogue ----------------
    if (MODE == 3) {
        float bsv[8], gv[8], bv[8];
#pragma unroll
        for (int j = 0; j < 8; j++) {
            bsv[j] = bias[tn0 + j];
            gv[j]  = lng[tn0 + j];
            bv[j]  = lnb[tn0 + j];
        }
#pragma unroll
        for (int p = 0; p < 4; p++) {
            float rowv[2][8];
#pragma unroll
            for (int j = 0; j < 8; j++) {
                float2 v = unpack2(acc2[p][j]);
                rowv[0][j] = v.x; rowv[1][j] = v.y;
            }
#pragma unroll
            for (int s = 0; s < 2; s++) {
                size_t m = (size_t)(row0 + tm0 + 2 * p + s);
                float out[8];
                const float4* rr4 = reinterpret_cast<const float4*>(
                    &resid[m * 128 + tn0]);
                float4 r0 = rr4[0], r1 = rr4[1];
                out[0] = rowv[s][0] + bsv[0] + r0.x;
                out[1] = rowv[s][1] + bsv[1] + r0.y;
                out[2] = rowv[s][2] + bsv[2] + r0.z;
                out[3] = rowv[s][3] + bsv[3] + r0.w;
                out[4] = rowv[s][4] + bsv[4] + r1.x;
                out[5] = rowv[s][5] + bsv[5] + r1.y;
                out[6] = rowv[s][6] + bsv[6] + r1.z;
                out[7] = rowv[s][7] + bsv[7] + r1.w;

                float rsum = 0.f;
#pragma unroll
                for (int j = 0; j < 8; j++) rsum += out[j];
#pragma unroll
                for (int off = 1; off < 16; off <<= 1)
                    rsum += __shfl_xor_sync(0xffffffffu, rsum, off);
                float mean = rsum * (1.f / 128.f);

                float sq = 0.f;
#pragma unroll
                for (int j = 0; j < 8; j++) {
                    out[j] -= mean;
                    sq += out[j] * out[j];
                }
#pragma unroll
                for (int off = 1; off < 16; off <<= 1)
                    sq += __shfl_xor_sync(0xffffffffu, sq, off);
                float rs = rsqrtf(sq * (1.f / 128.f) + 1e-5f);

                float o8[8];
#pragma unroll
                for (int j = 0; j < 8; j++)
                    o8[j] = out[j] * rs * gv[j] + bv[j];
                *reinterpret_cast<float4*>(&C[m * 128 + tn0]) =
                    make_float4(o8[0], o8[1], o8[2], o8[3]);
                *reinterpret_cast<float4*>(&C[m * 128 + tn0 + 4]) =
                    make_float4(o8[4], o8[5], o8[6], o8[7]);
            }
        }
    } else {
#pragma unroll
        for (int p = 0; p < 4; p++) {
            float rowv[2][8];
#pragma unroll
            for (int j = 0; j < 8; j++) {
                float2 v = unpack2(acc2[p][j]);
                rowv[0][j] = v.x; rowv[1][j] = v.y;
            }
#pragma unroll
            for (int s = 0; s < 2; s++) {
                size_t m = (size_t)(row0 + tm0 + 2 * p + s);
                float out[8];
#pragma unroll
                for (int j = 0; j < 8; j++) {
                    float v = rowv[s][j];
                    if (MODE >= 1) v += bias[n0 + tn0 + j];
                    if (MODE == 2) v = fmaxf(v, 0.f);
                    out[j] = v;
                }
                *reinterpret_cast<float4*>(&C[m * Nc + n0 + tn0]) =
                    make_float4(out[0], out[1], out[2], out[3]);
                *reinterpret_cast<float4*>(&C[m * Nc + n0 + tn0 + 4]) =
                    make_float4(out[4], out[5], out[6], out[7]);
            }
        }
    }
}

// ---------------------------------------------------------------------------
// Fused flash-style triangle attention (R12 float4 version — fastest).
// CTA = (b, i-pair): grid 256, 512 threads. thread = (i_loc, h, j).
// Online softmax in registers; k/v2 slices streamed via triple-buffered
// cp.async (stride-132 rows, 16B-aligned); q/v1 rows via broadcast buf.
// ---------------------------------------------------------------------------
#define KV_STRIDE 132
#define KV_SLICE  (64 * KV_STRIDE)
#define KV_PAIR   (2 * KV_SLICE)
#define QV_SLICE  (4 * 128)
#define ATTN_SMEM_FLOATS (3 * KV_PAIR + 3 * QV_SLICE)
#define ATTN_SMEM_BYTES  (ATTN_SMEM_FLOATS * 4)   // 208896 B

__global__ __launch_bounds__(512) void attn_kernel(
    const float* __restrict__ qkv, float* __restrict__ o)
{
    extern __shared__ float sm[];
    float* kv = sm;                        // [3][2][64][132]
    float* qv = sm + 3 * KV_PAIR;          // [3][4][128]

    const int tid = threadIdx.x;
    const int cta = blockIdx.x;            // b*32 + ipair
    const int b   = cta >> 5;
    const int i0  = (cta & 31) * 2;

    const int i_loc = tid >> 8;            // 0/1
    const int h     = (tid >> 6) & 3;
    const int j     = tid & 63;
    const int ig    = i0 + i_loc;

    auto issue = [&](int l, int bs) {
        uint32_t kvb = (uint32_t)__cvta_generic_to_shared(kv + bs * KV_PAIR);
        const float* src_base = qkv + (size_t)(b * 64 + l) * 64 * 512;
#pragma unroll
        for (int u = 0; u < 8; u++) {
            int f4 = tid + u * 512;        // 0..4095
            int sl = f4 >> 11;             // 0 = k, 1 = v2
            int g  = f4 & 2047;
            int jj = g >> 5, c4 = g & 31;
            uint32_t dst = kvb +
                (uint32_t)(sl * KV_SLICE + jj * KV_STRIDE + c4 * 4) * 4u;
            cp16(dst, src_base + (size_t)jj * 512 + 128 + sl * 256 + c4 * 4);
        }
        if (tid < 128) {                   // q/v1 rows for both i's
            int idx = tid >> 5, c4 = tid & 31;
            int il = idx >> 1, qsel = idx & 1;   // 0=q, 1=v1
            uint32_t dst = (uint32_t)__cvta_generic_to_shared(
                qv + bs * QV_SLICE + idx * 128 + c4 * 4);
            cp16(dst, qkv + (size_t)((b * 64 + i0 + il) * 64 + l) * 512
                          + qsel * 256 + c4 * 4);
        }
    };

    issue(0, 0); cp_commit();
    issue(1, 1); cp_commit();

    float4 acc[8];
#pragma unroll
    for (int u = 0; u < 8; u++) acc[u] = make_float4(0.f, 0.f, 0.f, 0.f);
    float mmax = -1e30f, ssum = 0.f;
    const float inv_scale = 0.17677669529663687f;   // 1/sqrt(32)

    for (int l = 0; l < 64; l++) {
        if (l < 63) cp_wait<1>(); else cp_wait<0>();
        __syncthreads();                    // slice l visible; l-1 readers done
        if (l + 2 < 64) { issue(l + 2, (l + 2) % 3); cp_commit(); }

        const float* kb   = kv + (l % 3) * KV_PAIR;
        const float* qvb  = qv + (l % 3) * QV_SLICE;
        const float4* kp  = (const float4*)(kb + j * KV_STRIDE + h * 32);
        const float4* v2p = (const float4*)(kb + KV_SLICE + j * KV_STRIDE + h * 32);
        const float4* qp  = (const float4*)(qvb + (i_loc * 2) * 128 + h * 32);
        const float4* v1p = (const float4*)(qvb + (i_loc * 2 + 1) * 128 + h * 32);

        float d0 = 0.f, d1 = 0.f, d2 = 0.f, d3 = 0.f;
#pragma unroll
        for (int u = 0; u < 8; u++) {
            float4 kq = kp[u], qq = qp[u];
            d0 = fmaf(qq.x, kq.x, d0); d1 = fmaf(qq.y, kq.y, d1);
            d2 = fmaf(qq.z, kq.z, d2); d3 = fmaf(qq.w, kq.w, d3);
        }
        float s = ((d0 + d1) + (d2 + d3)) * inv_scale;

        float p;
        if (s > mmax) {                     // new running max: rescale
            float corr = __expf(mmax - s);
            mmax = s;
            ssum *= corr;
#pragma unroll
            for (int u = 0; u < 8; u++) {
                acc[u].x *= corr; acc[u].y *= corr;
                acc[u].z *= corr; acc[u].w *= corr;
            }
            p = 1.f;
        } else {
            p = __expf(s - mmax);
        }
        ssum += p;

#pragma unroll
        for (int u = 0; u < 8; u++) {
            float4 a = v1p[u], v = v2p[u];
            acc[u].x = fmaf(p * a.x, v.x, acc[u].x);
            acc[u].y = fmaf(p * a.y, v.y, acc[u].y);
            acc[u].z = fmaf(p * a.z, v.z, acc[u].z);
            acc[u].w = fmaf(p * a.w, v.w, acc[u].w);
        }
    }

    float inv = 1.f / ssum;
    float4* ob = (float4*)(o + ((size_t)(b * 64 + ig) * 64 + j) * 128 + h * 32);
#pragma unroll
    for (int u = 0; u < 8; u++) {
        acc[u].x *= inv; acc[u].y *= inv; acc[u].z *= inv; acc[u].w *= inv;
        ob[u] = acc[u];
    }
}

// ---------------------------------------------------------------------------
// out[b*N+i] = diag_token(b,i) . Wout + bout
// ---------------------------------------------------------------------------
__global__ __launch_bounds__(128) void out_kernel(
    const float* __restrict__ tok, const float* __restrict__ Wout,
    const float* __restrict__ bout, float* __restrict__ out)
{
    __shared__ float red[4];
    int bi = blockIdx.x;
    int c  = threadIdx.x;
    int token = bi * NN + (bi & 63);

    float s = tok[(size_t)token * DD + c] * Wout[c];
#pragma unroll
    for (int o_ = 16; o_ > 0; o_ >>= 1) s += __shfl_xor_sync(0xffffffffu, s, o_);
    if ((c & 31) == 0) red[c >> 5] = s;
    __syncthreads();
    if (c == 0) out[bi] = red[0] + red[1] + red[2] + red[3] + bout[0];
}

// ---------------------------------------------------------------------------
// kernel_launch
// ---------------------------------------------------------------------------
extern "C" void kernel_launch(void* const* d_in, const int* in_sizes, int n_in,
                              void* d_out, int out_size)
{
    (void)in_sizes; (void)n_in; (void)out_size;

    const float* x    = (const float*)d_in[0];
    const float* ea   = (const float*)d_in[1];
    const int*   mask = (const int*)  d_in[2];
    const float* nW   = (const float*)d_in[3];
    const float* nb   = (const float*)d_in[4];
    const float* eW   = (const float*)d_in[5];
    const float* eb   = (const float*)d_in[6];
    const float* noe  = (const float*)d_in[7];
    const float* Wq   = (const float*)d_in[8];
    const float* Wk   = (const float*)d_in[9];
    const float* Wv1  = (const float*)d_in[10];
    const float* Wv2  = (const float*)d_in[11];
    const float* Wo   = (const float*)d_in[12];
    const float* bo   = (const float*)d_in[13];
    const float* ln1g = (const float*)d_in[14];
    const float* ln1b = (const float*)d_in[15];
    const float* W1   = (const float*)d_in[16];
    const float* b1   = (const float*)d_in[17];
    const float* W2   = (const float*)d_in[18];
    const float* b2   = (const float*)d_in[19];
    const float* ln2g = (const float*)d_in[20];
    const float* ln2b = (const float*)d_in[21];
    const float* Wout = (const float*)d_in[22];
    const float* bout = (const float*)d_in[23];

    float *p_tok, *p_big, *p_o, *p_wpk;
    cudaGetSymbolAddress((void**)&p_tok, g_tok);
    cudaGetSymbolAddress((void**)&p_big, g_big);
    cudaGetSymbolAddress((void**)&p_o,   g_o);
    cudaGetSymbolAddress((void**)&p_wpk, g_wpk);

    cudaFuncSetAttribute(attn_kernel,
        cudaFuncAttributeMaxDynamicSharedMemorySize, ATTN_SMEM_BYTES);

    pack_w_kernel<<<LL * DD, 512>>>(Wq, Wk, Wv1, Wv2, p_wpk);
    embed_kernel<<<TT, 128>>>(x, ea, mask, nW, nb, eW, eb, noe, p_tok);

    const dim3 gN128(1, TT / 64);   // Nc = 128
    const dim3 gN512(4, TT / 64);   // Nc = 512

    for (int l = 0; l < LL; l++) {
        const float* wqkv = p_wpk + (size_t)l * DD * 512;
        const float* wo   = Wo   + (size_t)l * DD * DD;
        const float* bol  = bo   + (size_t)l * DD;
        const float* g1   = ln1g + (size_t)l * DD;
        const float* bb1  = ln1b + (size_t)l * DD;
        const float* w1   = W1   + (size_t)l * DD * FFD;
        const float* bf1  = b1   + (size_t)l * FFD;
        const float* w2   = W2   + (size_t)l * FFD * DD;
        const float* bf2  = b2   + (size_t)l * DD;
        const float* g2   = ln2g + (size_t)l * DD;
        const float* bb2  = ln2b + (size_t)l * DD;

        // fused QKV projection: [TT,128] @ [128,512] -> g_big
        gemm_kernel<0><<<gN512, 128>>>(p_tok, wqkv, nullptr, p_big,
                                       TT, DD, 4 * DD, nullptr, nullptr, nullptr);

        attn_kernel<<<BB * NN / 2, 512, ATTN_SMEM_BYTES>>>(p_big, p_o);

        // tok = LN(tok + o@Wo + bo)   (fused epilogue)
        gemm_kernel<3><<<gN128, 128>>>(p_o, wo, bol, p_tok,
                                       TT, DD, DD, p_tok, g1, bb1);

        // FFN hidden: relu(tok@W1 + b1)
        gemm_kernel<2><<<gN512, 128>>>(p_tok, w1, bf1, p_big,
                                       TT, DD, FFD, nullptr, nullptr, nullptr);

        // tok = LN(tok + hidden@W2 + b2)   (fused epilogue)
        gemm_kernel<3><<<gN128, 128>>>(p_big, w2, bf2, p_tok,
                                       TT, FFD, DD, p_tok, g2, bb2);
    }

    out_kernel<<<BB * NN, 128>>>(p_tok, Wout, bout, (float*)d_out);
}

// round 15
// speedup vs baseline: 2.4312x; 2.4312x over previous
#include <cuda_runtime.h>
#include <cuda_bf16.h>
#include <cstddef>
#include <cstdint>

// ---------------------------------------------------------------------------
// Problem constants
// ---------------------------------------------------------------------------
#define BB   8
#define NN   64
#define TT   (BB * NN * NN)      // 32768 tokens
#define DD   128
#define HH   4
#define DHH  32
#define LL   3
#define FFD  512

// QKV offsets inside fused 512-wide projection
#define Q_OFF   0
#define K_OFF   128
#define V1_OFF  256
#define V2_OFF  384

static __device__ float g_tok [TT * DD];    // token buffer       (16 MB)
static __device__ float g_big [TT * FFD];   // QKV fused / FFN hidden (64 MB)
static __device__ float g_o   [TT * DD];    // attention output   (16 MB)
static __device__ float g_wpk [LL * DD * 4 * DD];  // packed QKV weights

// ---------------------------------------------------------------------------
// cp.async helpers
// ---------------------------------------------------------------------------
__device__ __forceinline__ void cp16(uint32_t dst, const void* src) {
    asm volatile("cp.async.cg.shared.global [%0], [%1], 16;\n"
                 :: "r"(dst), "l"(src) : "memory");
}
__device__ __forceinline__ void cp_commit() {
    asm volatile("cp.async.commit_group;\n" ::: "memory");
}
template <int N> __device__ __forceinline__ void cp_wait() {
    asm volatile("cp.async.wait_group %0;\n" :: "n"(N) : "memory");
}

// ---------------------------------------------------------------------------
// packed f32x2 helpers (Blackwell FFMA2 path; exact fp32 semantics)
// ---------------------------------------------------------------------------
__device__ __forceinline__ unsigned long long splat2(float v) {
    unsigned long long r; uint32_t u = __float_as_uint(v);
    asm("mov.b64 %0, {%1, %1};" : "=l"(r) : "r"(u));
    return r;
}
__device__ __forceinline__ unsigned long long fma2(
    unsigned long long a, unsigned long long b, unsigned long long c) {
    unsigned long long d;
    asm("fma.rn.f32x2 %0, %1, %2, %3;" : "=l"(d) : "l"(a), "l"(b), "l"(c));
    return d;
}
__device__ __forceinline__ float2 unpack2(unsigned long long v) {
    uint32_t lo, hi;
    asm("mov.b64 {%0, %1}, %2;" : "=r"(lo), "=r"(hi) : "l"(v));
    return make_float2(__uint_as_float(lo), __uint_as_float(hi));
}
__device__ __forceinline__ unsigned long long d2ll(double v) {
    return __double_as_longlong(v);
}

// ---------------------------------------------------------------------------
// Pack Wq|Wk|Wv1|Wv2 -> wpack[l][k][512]
// ---------------------------------------------------------------------------
__global__ __launch_bounds__(512) void pack_w_kernel(
    const float* __restrict__ Wq, const float* __restrict__ Wk,
    const float* __restrict__ Wv1, const float* __restrict__ Wv2,
    float* __restrict__ wpk)
{
    int lk = blockIdx.x;           // l*128 + k
    int l  = lk >> 7;
    int k  = lk & 127;
    int n  = threadIdx.x;          // 0..511
    int c  = n & 127;
    const float* src;
    switch (n >> 7) {
        case 0:  src = Wq;  break;
        case 1:  src = Wk;  break;
        case 2:  src = Wv1; break;
        default: src = Wv2; break;
    }
    wpk[(size_t)lk * 512 + n] = src[(size_t)l * DD * DD + k * DD + c];
}

// ---------------------------------------------------------------------------
// Embedding: tok[b,i,j,:] = node/edge/no_edge
// ---------------------------------------------------------------------------
__global__ __launch_bounds__(128) void embed_kernel(
    const float* __restrict__ x, const float* __restrict__ ea,
    const int*   __restrict__ mask,
    const float* __restrict__ nW, const float* __restrict__ nb,
    const float* __restrict__ eW, const float* __restrict__ eb,
    const float* __restrict__ noe, float* __restrict__ tok)
{
    int t = blockIdx.x;
    int d = threadIdx.x;
    int b = t >> 12;
    int i = (t >> 6) & 63;
    int j = t & 63;

    float val;
    if (i == j) {
        val = nb[d];
        const float* xr = x + (size_t)(b * NN + i) * 16;
#pragma unroll
        for (int c = 0; c < 16; c++) val = fmaf(xr[c], nW[c * DD + d], val);
    } else if (mask[t] != 0) {
        val = eb[d];
        const float* er = ea + (size_t)t * 8;
#pragma unroll
        for (int c = 0; c < 8; c++) val = fmaf(er[c], eW[c * DD + d], val);
    } else {
        val = noe[d];
    }
    tok[(size_t)t * DD + d] = val;
}

// ---------------------------------------------------------------------------
// Tiled fp32 GEMM with packed-f32x2 inner loop (R13 version — known fast).
// MODE: 0 plain, 1 +bias, 2 +bias+relu, 3 +bias+residual+LayerNorm (Nc==128,
// single n-block: each CTA owns complete token rows).
// 64(M) x 128(N) tile, BK=16, 128 threads, 8x8 thread tile, double-buffered.
// ---------------------------------------------------------------------------
template <int MODE>
__global__ __launch_bounds__(128) void gemm_kernel(
    const float* __restrict__ A, const float* __restrict__ W,
    const float* __restrict__ bias, float* __restrict__ C,
    int M, int K, int Nc,
    const float* __restrict__ resid,   // MODE 3: residual input
    const float* __restrict__ lng,     // MODE 3: LN gamma
    const float* __restrict__ lnb)     // MODE 3: LN beta
{
    __shared__ float As[2][16][68];
    __shared__ float Bs[2][16][128];

    int tid  = threadIdx.x;
    int row0 = blockIdx.y * 64;
    int n0   = blockIdx.x * 128;

    int tx = tid & 15, ty = tid >> 4;
    int tm0 = ty * 8, tn0 = tx * 8;

    unsigned long long acc2[8][4];
#pragma unroll
    for (int i = 0; i < 8; i++)
#pragma unroll
        for (int j = 0; j < 4; j++) acc2[i][j] = 0ull;

    int ar  = tid >> 2;
    int ac4 = tid & 3;
    int br  = tid >> 5;
    int bc4 = tid & 31;

    float4 areg[2], breg[4];
    const int NIT = K >> 4;

#pragma unroll
    for (int rr = 0; rr < 2; rr++)
        areg[rr] = *reinterpret_cast<const float4*>(
            &A[(size_t)(row0 + ar + rr * 32) * K + ac4 * 4]);
#pragma unroll
    for (int rr = 0; rr < 4; rr++)
        breg[rr] = *reinterpret_cast<const float4*>(
            &W[(size_t)(br + rr * 4) * Nc + n0 + bc4 * 4]);
#pragma unroll
    for (int rr = 0; rr < 2; rr++) {
        int m = ar + rr * 32;
        As[0][ac4 * 4 + 0][m] = areg[rr].x;
        As[0][ac4 * 4 + 1][m] = areg[rr].y;
        As[0][ac4 * 4 + 2][m] = areg[rr].z;
        As[0][ac4 * 4 + 3][m] = areg[rr].w;
    }
#pragma unroll
    for (int rr = 0; rr < 4; rr++)
        *reinterpret_cast<float4*>(&Bs[0][br + rr * 4][bc4 * 4]) = breg[rr];
    __syncthreads();

    for (int it = 0; it < NIT; it++) {
        int cur = it & 1;
        if (it + 1 < NIT) {
            int k0 = (it + 1) << 4;
#pragma unroll
            for (int rr = 0; rr < 2; rr++)
                areg[rr] = *reinterpret_cast<const float4*>(
                    &A[(size_t)(row0 + ar + rr * 32) * K + k0 + ac4 * 4]);
#pragma unroll
            for (int rr = 0; rr < 4; rr++)
                breg[rr] = *reinterpret_cast<const float4*>(
                    &W[(size_t)(k0 + br + rr * 4) * Nc + n0 + bc4 * 4]);
        }
#pragma unroll
        for (int k = 0; k < 16; k++) {
            float4 al = *reinterpret_cast<const float4*>(&As[cur][k][tm0]);
            float4 ah = *reinterpret_cast<const float4*>(&As[cur][k][tm0 + 4]);
            const double* bd = reinterpret_cast<const double*>(&Bs[cur][k][tn0]);
            unsigned long long b2r[4];
#pragma unroll
            for (int j = 0; j < 4; j++) b2r[j] = d2ll(bd[j]);

            unsigned long long a2s[8];
            a2s[0] = splat2(al.x); a2s[1] = splat2(al.y);
            a2s[2] = splat2(al.z); a2s[3] = splat2(al.w);
            a2s[4] = splat2(ah.x); a2s[5] = splat2(ah.y);
            a2s[6] = splat2(ah.z); a2s[7] = splat2(ah.w);
#pragma unroll
            for (int i = 0; i < 8; i++)
#pragma unroll
                for (int j = 0; j < 4; j++)
                    acc2[i][j] = fma2(a2s[i], b2r[j], acc2[i][j]);
        }
        if (it + 1 < NIT) {
            int nxt = cur ^ 1;
#pragma unroll
            for (int rr = 0; rr < 2; rr++) {
                int m = ar + rr * 32;
                As[nxt][ac4 * 4 + 0][m] = areg[rr].x;
                As[nxt][ac4 * 4 + 1][m] = areg[rr].y;
                As[nxt][ac4 * 4 + 2][m] = areg[rr].z;
                As[nxt][ac4 * 4 + 3][m] = areg[rr].w;
            }
#pragma unroll
            for (int rr = 0; rr < 4; rr++)
                *reinterpret_cast<float4*>(&Bs[nxt][br + rr * 4][bc4 * 4]) = breg[rr];
        }
        __syncthreads();
    }

    // ---------------- epilogue ----------------
    if (MODE == 3) {
        float bsv[8], gv[8], bv[8];
#pragma unroll
        for (int j = 0; j < 8; j++) {
            bsv[j] = bias[tn0 + j];
            gv[j]  = lng[tn0 + j];
            bv[j]  = lnb[tn0 + j];
        }
#pragma unroll
        for (int i = 0; i < 8; i++) {
            size_t m = (size_t)(row0 + tm0 + i);
            float out[8];
#pragma unroll
            for (int j = 0; j < 4; j++) {
                float2 p = unpack2(acc2[i][j]);
                out[2 * j] = p.x; out[2 * j + 1] = p.y;
            }
            const float4* rr4 = reinterpret_cast<const float4*>(
                &resid[m * 128 + tn0]);
            float4 r0 = rr4[0], r1 = rr4[1];
            out[0] += bsv[0] + r0.x; out[1] += bsv[1] + r0.y;
            out[2] += bsv[2] + r0.z; out[3] += bsv[3] + r0.w;
            out[4] += bsv[4] + r1.x; out[5] += bsv[5] + r1.y;
            out[6] += bsv[6] + r1.z; out[7] += bsv[7] + r1.w;

            float rsum = 0.f;
#pragma unroll
            for (int j = 0; j < 8; j++) rsum += out[j];
#pragma unroll
            for (int off = 1; off < 16; off <<= 1)
                rsum += __shfl_xor_sync(0xffffffffu, rsum, off);
            float mean = rsum * (1.f / 128.f);

            float sq = 0.f;
#pragma unroll
            for (int j = 0; j < 8; j++) {
                out[j] -= mean;
                sq += out[j] * out[j];
            }
#pragma unroll
            for (int off = 1; off < 16; off <<= 1)
                sq += __shfl_xor_sync(0xffffffffu, sq, off);
            float rs = rsqrtf(sq * (1.f / 128.f) + 1e-5f);

            float o8[8];
#pragma unroll
            for (int j = 0; j < 8; j++)
                o8[j] = out[j] * rs * gv[j] + bv[j];
            *reinterpret_cast<float4*>(&C[m * 128 + tn0]) =
                make_float4(o8[0], o8[1], o8[2], o8[3]);
            *reinterpret_cast<float4*>(&C[m * 128 + tn0 + 4]) =
                make_float4(o8[4], o8[5], o8[6], o8[7]);
        }
    } else {
#pragma unroll
        for (int i = 0; i < 8; i++) {
            size_t m = (size_t)(row0 + tm0 + i);
            float out[8];
#pragma unroll
            for (int j = 0; j < 4; j++) {
                float2 p = unpack2(acc2[i][j]);
                out[2 * j] = p.x; out[2 * j + 1] = p.y;
            }
#pragma unroll
            for (int j = 0; j < 8; j++) {
                if (MODE >= 1) out[j] += bias[n0 + tn0 + j];
                if (MODE == 2) out[j] = fmaxf(out[j], 0.f);
            }
            *reinterpret_cast<float4*>(&C[m * Nc + n0 + tn0]) =
                make_float4(out[0], out[1], out[2], out[3]);
            *reinterpret_cast<float4*>(&C[m * Nc + n0 + tn0 + 4]) =
                make_float4(out[4], out[5], out[6], out[7]);
        }
    }
}

// ---------------------------------------------------------------------------
// Fused flash-style triangle attention, 4 i's per CTA / 2 per thread.
// grid = 128 CTAs (b, i-quad) -> exactly one wave on 148 SMs.
// 512 threads: thread = (i_pair, h, j), handles i = i0 + i_pair*2 + {0,1}.
// k/v2 smem reads shared across the thread's two i's.
// smem: 3*KV_PAIR + 3*QV4 = 215040 B.
// ---------------------------------------------------------------------------
#define KV_STRIDE 132
#define KV_SLICE  (64 * KV_STRIDE)
#define KV_PAIR   (2 * KV_SLICE)
#define QV4_SLICE (8 * 128)                 // (q,v1) x 4 i
#define ATTN_SMEM_FLOATS (3 * KV_PAIR + 3 * QV4_SLICE)
#define ATTN_SMEM_BYTES  (ATTN_SMEM_FLOATS * 4)   // 215040 B

__global__ __launch_bounds__(512, 1) void attn_kernel(
    const float* __restrict__ qkv, float* __restrict__ o)
{
    extern __shared__ float sm[];
    float* kv = sm;                        // [3][2][64][132]
    float* qv = sm + 3 * KV_PAIR;          // [3][8][128]

    const int tid = threadIdx.x;
    const int cta = blockIdx.x;            // b*16 + iquad
    const int b   = cta >> 4;
    const int i0  = (cta & 15) * 4;

    const int ip = tid >> 8;               // i-pair 0/1
    const int h  = (tid >> 6) & 3;
    const int j  = tid & 63;

    auto issue = [&](int l, int bs) {
        uint32_t kvb = (uint32_t)__cvta_generic_to_shared(kv + bs * KV_PAIR);
        const float* src_base = qkv + (size_t)(b * 64 + l) * 64 * 512;
#pragma unroll
        for (int u = 0; u < 8; u++) {
            int f4 = tid + u * 512;        // 0..4095
            int sl = f4 >> 11;             // 0 = k, 1 = v2
            int g  = f4 & 2047;
            int jj = g >> 5, c4 = g & 31;
            uint32_t dst = kvb +
                (uint32_t)(sl * KV_SLICE + jj * KV_STRIDE + c4 * 4) * 4u;
            cp16(dst, src_base + (size_t)jj * 512 + 128 + sl * 256 + c4 * 4);
        }
        if (tid < 256) {                   // q/v1 rows for 4 i's
            int idx = tid >> 5, c4 = tid & 31;   // idx 0..7
            int il = idx >> 1, qsel = idx & 1;   // 0=q, 1=v1
            uint32_t dst = (uint32_t)__cvta_generic_to_shared(
                qv + bs * QV4_SLICE + idx * 128 + c4 * 4);
            cp16(dst, qkv + (size_t)((b * 64 + i0 + il) * 64 + l) * 512
                          + qsel * 256 + c4 * 4);
        }
    };

    issue(0, 0); cp_commit();
    issue(1, 1); cp_commit();

    float4 acc[2][8];
#pragma unroll
    for (int s = 0; s < 2; s++)
#pragma unroll
        for (int u = 0; u < 8; u++) acc[s][u] = make_float4(0.f, 0.f, 0.f, 0.f);
    float mmax[2] = {-1e30f, -1e30f};
    float ssum[2] = {0.f, 0.f};
    const float inv_scale = 0.17677669529663687f;   // 1/sqrt(32)

    for (int l = 0; l < 64; l++) {
        if (l < 63) cp_wait<1>(); else cp_wait<0>();
        __syncthreads();                    // slice l visible; l-1 readers done
        if (l + 2 < 64) { issue(l + 2, (l + 2) % 3); cp_commit(); }

        const float* kb  = kv + (l % 3) * KV_PAIR;
        const float* qvb = qv + (l % 3) * QV4_SLICE;
        const float4* kp  = (const float4*)(kb + j * KV_STRIDE + h * 32);
        const float4* v2p = (const float4*)(kb + KV_SLICE + j * KV_STRIDE + h * 32);
        // rows for the thread's two i's: il = ip*2 + s
        const float4* qp0  = (const float4*)(qvb + (ip * 2 + 0) * 2 * 128 + h * 32);
        const float4* v1p0 = (const float4*)(qvb + ((ip * 2 + 0) * 2 + 1) * 128 + h * 32);
        const float4* qp1  = (const float4*)(qvb + (ip * 2 + 1) * 2 * 128 + h * 32);
        const float4* v1p1 = (const float4*)(qvb + ((ip * 2 + 1) * 2 + 1) * 128 + h * 32);

        // ---- dots for both i's, k loaded once ----
        float a0 = 0.f, a1 = 0.f, a2 = 0.f, a3 = 0.f;
        float b0 = 0.f, b1 = 0.f, b2 = 0.f, b3 = 0.f;
#pragma unroll
        for (int u = 0; u < 8; u++) {
            float4 kq = kp[u];
            float4 q0 = qp0[u], q1 = qp1[u];
            a0 = fmaf(q0.x, kq.x, a0); a1 = fmaf(q0.y, kq.y, a1);
            a2 = fmaf(q0.z, kq.z, a2); a3 = fmaf(q0.w, kq.w, a3);
            b0 = fmaf(q1.x, kq.x, b0); b1 = fmaf(q1.y, kq.y, b1);
            b2 = fmaf(q1.z, kq.z, b2); b3 = fmaf(q1.w, kq.w, b3);
        }
        float s0 = ((a0 + a1) + (a2 + a3)) * inv_scale;
        float s1 = ((b0 + b1) + (b2 + b3)) * inv_scale;

        float p0, p1;
        if (s0 > mmax[0]) {
            float corr = __expf(mmax[0] - s0);
            mmax[0] = s0; ssum[0] *= corr;
#pragma unroll
            for (int u = 0; u < 8; u++) {
                acc[0][u].x *= corr; acc[0][u].y *= corr;
                acc[0][u].z *= corr; acc[0][u].w *= corr;
            }
            p0 = 1.f;
        } else p0 = __expf(s0 - mmax[0]);
        ssum[0] += p0;

        if (s1 > mmax[1]) {
            float corr = __expf(mmax[1] - s1);
            mmax[1] = s1; ssum[1] *= corr;
#pragma unroll
            for (int u = 0; u < 8; u++) {
                acc[1][u].x *= corr; acc[1][u].y *= corr;
                acc[1][u].z *= corr; acc[1][u].w *= corr;
            }
            p1 = 1.f;
        } else p1 = __expf(s1 - mmax[1]);
        ssum[1] += p1;

        // ---- accumulate, v2 loaded once ----
#pragma unroll
        for (int u = 0; u < 8; u++) {
            float4 v  = v2p[u];
            float4 w0 = v1p0[u], w1 = v1p1[u];
            acc[0][u].x = fmaf(p0 * w0.x, v.x, acc[0][u].x);
            acc[0][u].y = fmaf(p0 * w0.y, v.y, acc[0][u].y);
            acc[0][u].z = fmaf(p0 * w0.z, v.z, acc[0][u].z);
            acc[0][u].w = fmaf(p0 * w0.w, v.w, acc[0][u].w);
            acc[1][u].x = fmaf(p1 * w1.x, v.x, acc[1][u].x);
            acc[1][u].y = fmaf(p1 * w1.y, v.y, acc[1][u].y);
            acc[1][u].z = fmaf(p1 * w1.z, v.z, acc[1][u].z);
            acc[1][u].w = fmaf(p1 * w1.w, v.w, acc[1][u].w);
        }
    }

#pragma unroll
    for (int s = 0; s < 2; s++) {
        int ig = i0 + ip * 2 + s;
        float inv = 1.f / ssum[s];
        float4* ob = (float4*)(o + ((size_t)(b * 64 + ig) * 64 + j) * 128 + h * 32);
#pragma unroll
        for (int u = 0; u < 8; u++) {
            float4 v = acc[s][u];
            v.x *= inv; v.y *= inv; v.z *= inv; v.w *= inv;
            ob[u] = v;
        }
    }
}

// ---------------------------------------------------------------------------
// out[b*N+i] = diag_token(b,i) . Wout + bout
// ---------------------------------------------------------------------------
__global__ __launch_bounds__(128) void out_kernel(
    const float* __restrict__ tok, const float* __restrict__ Wout,
    const float* __restrict__ bout, float* __restrict__ out)
{
    __shared__ float red[4];
    int bi = blockIdx.x;
    int c  = threadIdx.x;
    int token = bi * NN + (bi & 63);

    float s = tok[(size_t)token * DD + c] * Wout[c];
#pragma unroll
    for (int o_ = 16; o_ > 0; o_ >>= 1) s += __shfl_xor_sync(0xffffffffu, s, o_);
    if ((c & 31) == 0) red[c >> 5] = s;
    __syncthreads();
    if (c == 0) out[bi] = red[0] + red[1] + red[2] + red[3] + bout[0];
}

// ---------------------------------------------------------------------------
// kernel_launch
// ---------------------------------------------------------------------------
extern "C" void kernel_launch(void* const* d_in, const int* in_sizes, int n_in,
                              void* d_out, int out_size)
{
    (void)in_sizes; (void)n_in; (void)out_size;

    const float* x    = (const float*)d_in[0];
    const float* ea   = (const float*)d_in[1];
    const int*   mask = (const int*)  d_in[2];
    const float* nW   = (const float*)d_in[3];
    const float* nb   = (const float*)d_in[4];
    const float* eW   = (const float*)d_in[5];
    const float* eb   = (const float*)d_in[6];
    const float* noe  = (const float*)d_in[7];
    const float* Wq   = (const float*)d_in[8];
    const float* Wk   = (const float*)d_in[9];
    const float* Wv1  = (const float*)d_in[10];
    const float* Wv2  = (const float*)d_in[11];
    const float* Wo   = (const float*)d_in[12];
    const float* bo   = (const float*)d_in[13];
    const float* ln1g = (const float*)d_in[14];
    const float* ln1b = (const float*)d_in[15];
    const float* W1   = (const float*)d_in[16];
    const float* b1   = (const float*)d_in[17];
    const float* W2   = (const float*)d_in[18];
    const float* b2   = (const float*)d_in[19];
    const float* ln2g = (const float*)d_in[20];
    const float* ln2b = (const float*)d_in[21];
    const float* Wout = (const float*)d_in[22];
    const float* bout = (const float*)d_in[23];

    float *p_tok, *p_big, *p_o, *p_wpk;
    cudaGetSymbolAddress((void**)&p_tok, g_tok);
    cudaGetSymbolAddress((void**)&p_big, g_big);
    cudaGetSymbolAddress((void**)&p_o,   g_o);
    cudaGetSymbolAddress((void**)&p_wpk, g_wpk);

    cudaFuncSetAttribute(attn_kernel,
        cudaFuncAttributeMaxDynamicSharedMemorySize, ATTN_SMEM_BYTES);

    pack_w_kernel<<<LL * DD, 512>>>(Wq, Wk, Wv1, Wv2, p_wpk);
    embed_kernel<<<TT, 128>>>(x, ea, mask, nW, nb, eW, eb, noe, p_tok);

    const dim3 gN128(1, TT / 64);   // Nc = 128
    const dim3 gN512(4, TT / 64);   // Nc = 512

    for (int l = 0; l < LL; l++) {
        const float* wqkv = p_wpk + (size_t)l * DD * 512;
        const float* wo   = Wo   + (size_t)l * DD * DD;
        const float* bol  = bo   + (size_t)l * DD;
        const float* g1   = ln1g + (size_t)l * DD;
        const float* bb1  = ln1b + (size_t)l * DD;
        const float* w1   = W1   + (size_t)l * DD * FFD;
        const float* bf1  = b1   + (size_t)l * FFD;
        const float* w2   = W2   + (size_t)l * FFD * DD;
        const float* bf2  = b2   + (size_t)l * DD;
        const float* g2   = ln2g + (size_t)l * DD;
        const float* bb2  = ln2b + (size_t)l * DD;

        // fused QKV projection: [TT,128] @ [128,512] -> g_big
        gemm_kernel<0><<<gN512, 128>>>(p_tok, wqkv, nullptr, p_big,
                                       TT, DD, 4 * DD, nullptr, nullptr, nullptr);

        attn_kernel<<<BB * NN / 4, 512, ATTN_SMEM_BYTES>>>(p_big, p_o);

        // tok = LN(tok + o@Wo + bo)   (fused epilogue)
        gemm_kernel<3><<<gN128, 128>>>(p_o, wo, bol, p_tok,
                                       TT, DD, DD, p_tok, g1, bb1);

        // FFN hidden: relu(tok@W1 + b1)
        gemm_kernel<2><<<gN512, 128>>>(p_tok, w1, bf1, p_big,
                                       TT, DD, FFD, nullptr, nullptr, nullptr);

        // tok = LN(tok + hidden@W2 + b2)   (fused epilogue)
        gemm_kernel<3><<<gN128, 128>>>(p_big, w2, bf2, p_tok,
                                       TT, FFD, DD, p_tok, g2, bb2);
    }

    out_kernel<<<BB * NN, 128>>>(p_tok, Wout, bout, (float*)d_out);
}